// round 2
// baseline (speedup 1.0000x reference)
#include <cuda_runtime.h>

// ---------------------------------------------------------------------------
// GATConv (PyG defaults: add_self_loops, negative_slope=0.2, concat=False)
//   h = x @ W            [N, H, C]
//   a_src/a_dst = <h, att>          [N, H]
//   alpha = softmax_dst(leaky(a_src[src]+a_dst[dst]))
//   out   = segsum_dst(alpha * h[src]); y = mean_h(out) + bias
//   result = relu(x + y)
// Shapes: N=50000, C=64, H=12, E=400000 (+N self loops)
// ---------------------------------------------------------------------------

namespace {
constexpr int CD = 64;    // channels
constexpr int HN = 12;    // heads
constexpr int HC = 768;   // HN * CD
constexpr int N_CAP = 50176;
constexpr int E_CAP = 460800;  // E + N with slack
}

// Scratch (device globals: allocation-free per harness rules)
__device__ float    g_h    [(size_t)N_CAP * HC];   // projected features
__device__ float    g_out  [(size_t)N_CAP * HC];   // aggregation accumulator
__device__ float    g_asrc [N_CAP * HN];
__device__ float    g_adst [N_CAP * HN];
__device__ unsigned g_max  [N_CAP * HN];           // ordered-uint encoded max
__device__ float    g_denom[N_CAP * HN];
__device__ float    g_alpha[(size_t)E_CAP * HN];

// Ordered-uint encoding so atomicMax(unsigned) == float max. enc is strictly
// monotone; buffer init 0 < enc(any float) and every dst has a self loop.
__device__ __forceinline__ unsigned encf(float f) {
    unsigned u = __float_as_uint(f);
    return (u & 0x80000000u) ? ~u : (u | 0x80000000u);
}
__device__ __forceinline__ float decf(unsigned u) {
    return (u & 0x80000000u) ? __uint_as_float(u ^ 0x80000000u)
                             : __uint_as_float(~u);
}

// ---------------------------------------------------------------------------
__global__ void k_zero(int nout4, int n12) {
    int i = blockIdx.x * blockDim.x + threadIdx.x;
    if (i < nout4) ((float4*)g_out)[i] = make_float4(0.f, 0.f, 0.f, 0.f);
    if (i < n12) { g_denom[i] = 0.f; g_max[i] = 0u; }
}

// ---------------------------------------------------------------------------
// GEMM: h[N, 768] = x[N, 64] @ W[64, 768].  Block: 128 rows x 64 cols, 256 thr,
// thread tile 8x4, full K=64 resident in smem.
__global__ void k_gemm(const float* __restrict__ x, const float* __restrict__ Wm,
                       int N) {
    __shared__ float xs[128][64];
    __shared__ float ws[64][64];
    int t = threadIdx.x;
    int brow = blockIdx.x * 128;
    int bcol = blockIdx.y * 64;

#pragma unroll
    for (int i = 0; i < 8; i++) {
        int v = i * 256 + t;            // float4 id within 128x64 tile
        int r = v >> 4;
        int k4 = v & 15;
        int gr = brow + r;
        float4 val = (gr < N) ? __ldg((const float4*)x + (size_t)gr * 16 + k4)
                              : make_float4(0.f, 0.f, 0.f, 0.f);
        *(float4*)&xs[r][k4 * 4] = val;
    }
#pragma unroll
    for (int i = 0; i < 4; i++) {
        int v = i * 256 + t;            // float4 id within 64x64 tile
        int k = v >> 4;
        int c4 = v & 15;
        *(float4*)&ws[k][c4 * 4] =
            __ldg((const float4*)Wm + (size_t)k * (HC / 4) + (bcol >> 2) + c4);
    }
    __syncthreads();

    int r0 = (t >> 4) * 8;
    int c0 = (t & 15) * 4;
    float acc[8][4] = {};
#pragma unroll
    for (int k = 0; k < 64; k++) {
        float4 b = *(const float4*)&ws[k][c0];
#pragma unroll
        for (int i = 0; i < 8; i++) {
            float a = xs[r0 + i][k];
            acc[i][0] += a * b.x;
            acc[i][1] += a * b.y;
            acc[i][2] += a * b.z;
            acc[i][3] += a * b.w;
        }
    }
#pragma unroll
    for (int i = 0; i < 8; i++) {
        int gr = brow + r0 + i;
        if (gr < N)
            *(float4*)&g_h[(size_t)gr * HC + bcol + c0] =
                make_float4(acc[i][0], acc[i][1], acc[i][2], acc[i][3]);
    }
}

// ---------------------------------------------------------------------------
// a_src[n,h] = sum_c h[n,h,c]*att_src[h,c]; same for a_dst. One warp per node.
__global__ void k_attn(const float* __restrict__ att_src,
                       const float* __restrict__ att_dst, int N) {
    int warp = (blockIdx.x * blockDim.x + threadIdx.x) >> 5;
    int lane = threadIdx.x & 31;
    if (warp >= N) return;
    const float2* hp = (const float2*)(g_h + (size_t)warp * HC);
#pragma unroll
    for (int h = 0; h < HN; h++) {
        float2 v = hp[h * 32 + lane];
        float2 as = __ldg((const float2*)att_src + h * 32 + lane);
        float2 ad = __ldg((const float2*)att_dst + h * 32 + lane);
        float ps = v.x * as.x + v.y * as.y;
        float pd = v.x * ad.x + v.y * ad.y;
#pragma unroll
        for (int o = 16; o; o >>= 1) {
            ps += __shfl_xor_sync(0xffffffffu, ps, o);
            pd += __shfl_xor_sync(0xffffffffu, pd, o);
        }
        if (lane == 0) {
            g_asrc[warp * HN + h] = ps;
            g_adst[warp * HN + h] = pd;
        }
    }
}

// ---------------------------------------------------------------------------
// Pass 1: alpha_raw = leaky_relu(a_src[src]+a_dst[dst]); segment max per dst.
__global__ void k_edge1(const int* __restrict__ ei, int E, int Etot) {
    int e = blockIdx.x * blockDim.x + threadIdx.x;
    if (e >= Etot) return;
    int s, d;
    if (e < E) { s = ei[e]; d = ei[E + e]; }
    else       { s = d = e - E; }

    float asv[HN], adv[HN];
    {
        const float4* ps = (const float4*)(g_asrc + s * HN);
        const float4* pd = (const float4*)(g_adst + d * HN);
        ((float4*)asv)[0] = ps[0]; ((float4*)asv)[1] = ps[1]; ((float4*)asv)[2] = ps[2];
        ((float4*)adv)[0] = pd[0]; ((float4*)adv)[1] = pd[1]; ((float4*)adv)[2] = pd[2];
    }
    float outv[HN];
#pragma unroll
    for (int h = 0; h < HN; h++) {
        float v = asv[h] + adv[h];
        v = (v > 0.f) ? v : 0.2f * v;
        outv[h] = v;
        atomicMax(&g_max[d * HN + h], encf(v));
    }
    float4* pa = (float4*)(g_alpha + (size_t)e * HN);
    pa[0] = ((float4*)outv)[0]; pa[1] = ((float4*)outv)[1]; pa[2] = ((float4*)outv)[2];
}

// ---------------------------------------------------------------------------
// Pass 2: alpha = exp(raw - max[dst]); segment sum denom per dst.
__global__ void k_edge2(const int* __restrict__ ei, int E, int Etot) {
    int e = blockIdx.x * blockDim.x + threadIdx.x;
    if (e >= Etot) return;
    int d;
    if (e < E) d = ei[E + e];
    else       d = e - E;

    float av[HN];
    {
        const float4* pa = (const float4*)(g_alpha + (size_t)e * HN);
        ((float4*)av)[0] = pa[0]; ((float4*)av)[1] = pa[1]; ((float4*)av)[2] = pa[2];
    }
    float ov[HN];
#pragma unroll
    for (int h = 0; h < HN; h++) {
        float m = decf(g_max[d * HN + h]);
        float a = expf(av[h] - m);
        ov[h] = a;
        atomicAdd(&g_denom[d * HN + h], a);
    }
    float4* pa = (float4*)(g_alpha + (size_t)e * HN);
    pa[0] = ((float4*)ov)[0]; pa[1] = ((float4*)ov)[1]; pa[2] = ((float4*)ov)[2];
}

// ---------------------------------------------------------------------------
// Pass 3: out[dst] += (alpha/denom) * h[src].  One warp per edge; 6 float4
// gathers + 24 scalar atomic adds per lane.
__global__ void k_edge3(const int* __restrict__ ei, int E, int Etot) {
    int gw = (blockIdx.x * blockDim.x + threadIdx.x) >> 5;
    int lane = threadIdx.x & 31;
    if (gw >= Etot) return;
    int s, d;
    if (gw < E) { s = ei[gw]; d = ei[E + gw]; }
    else        { s = d = gw - E; }

    float w = 0.f;
    if (lane < HN)
        w = g_alpha[(size_t)gw * HN + lane] / (g_denom[d * HN + lane] + 1e-16f);

    const float4* hs = (const float4*)(g_h + (size_t)s * HC);
    float* ob = g_out + (size_t)d * HC;
#pragma unroll
    for (int k2 = 0; k2 < 6; k2++) {
        int j4 = k2 * 32 + lane;                 // float4 index in [0,192)
        float wh = __shfl_sync(0xffffffffu, w, j4 >> 4);  // head = j4/16
        float4 v = hs[j4];
        int j = j4 * 4;
        atomicAdd(ob + j + 0, v.x * wh);
        atomicAdd(ob + j + 1, v.y * wh);
        atomicAdd(ob + j + 2, v.z * wh);
        atomicAdd(ob + j + 3, v.w * wh);
    }
}

// ---------------------------------------------------------------------------
// Finalize: y = mean_h(out) + bias; result = relu(x + y). One thread per float4.
__global__ void k_final(const float* __restrict__ x, const float* __restrict__ bias,
                        float* __restrict__ y, int N) {
    int idx = blockIdx.x * blockDim.x + threadIdx.x;   // float4 id, N*16 total
    if (idx >= N * 16) return;
    int n = idx >> 4;
    int c4 = idx & 15;
    const float* ob = g_out + (size_t)n * HC + c4 * 4;
    float4 acc = make_float4(0.f, 0.f, 0.f, 0.f);
#pragma unroll
    for (int h = 0; h < HN; h++) {
        float4 v = *(const float4*)(ob + h * CD);
        acc.x += v.x; acc.y += v.y; acc.z += v.z; acc.w += v.w;
    }
    const float inv = 1.0f / (float)HN;
    float4 xv = ((const float4*)x)[idx];
    float4 bv = __ldg((const float4*)bias + c4);
    float4 r;
    r.x = fmaxf(xv.x + acc.x * inv + bv.x, 0.f);
    r.y = fmaxf(xv.y + acc.y * inv + bv.y, 0.f);
    r.z = fmaxf(xv.z + acc.z * inv + bv.z, 0.f);
    r.w = fmaxf(xv.w + acc.w * inv + bv.w, 0.f);
    ((float4*)y)[idx] = r;
}

// ---------------------------------------------------------------------------
extern "C" void kernel_launch(void* const* d_in, const int* in_sizes, int n_in,
                              void* d_out, int out_size) {
    (void)n_in; (void)out_size;
    const float* x    = (const float*)d_in[0];
    const int*   ei   = (const int*)d_in[1];
    const float* Wm   = (const float*)d_in[2];
    const float* a_s  = (const float*)d_in[3];
    const float* a_d  = (const float*)d_in[4];
    const float* bias = (const float*)d_in[5];

    int N = in_sizes[0] / CD;
    int E = in_sizes[1] / 2;
    if (N > N_CAP) N = N_CAP;
    if (E + N > E_CAP) E = E_CAP - N;
    int Etot = E + N;

    int nz = N * (HC / 4);
    k_zero<<<(nz + 255) / 256, 256>>>(nz, N * HN);

    dim3 gg((N + 127) / 128, HC / 64);
    k_gemm<<<gg, 256>>>(x, Wm, N);

    k_attn<<<(N * 32 + 255) / 256, 256>>>(a_s, a_d, N);

    k_edge1<<<(Etot + 255) / 256, 256>>>(ei, E, Etot);
    k_edge2<<<(Etot + 255) / 256, 256>>>(ei, E, Etot);
    k_edge3<<<(Etot * 32 + 255) / 256, 256>>>(ei, E, Etot);

    k_final<<<(N * 16 + 255) / 256, 256>>>(x, bias, (float*)d_out, N);
}

// round 3
// speedup vs baseline: 2.8865x; 2.8865x over previous
#include <cuda_runtime.h>

// ---------------------------------------------------------------------------
// GATConv fused pipeline (CSR, atomic-free aggregation)
//   1. k_zero   : clear degree histogram
//   2. k_gemm   : h = x@W  (+ fused a_src/a_dst epilogue, one head per col-block)
//   3. k_hist   : degree[dst]++
//   4. k_scan1/2/3 : exclusive prefix sum -> CSR offsets (+ scatter cursors)
//   5. k_scatter: csr[pos[dst]++] = src
//   6. k_agg    : per-dst softmax + weighted gather + head mean + residual relu
// Shapes: N=50000, C=64, H=12, E=400000 (+N self loops)
// ---------------------------------------------------------------------------

namespace {
constexpr int CD = 64;
constexpr int HN = 12;
constexpr int HC = 768;
constexpr int N_CAP = 50176;
constexpr int E_CAP = 460800;
constexpr int SCAN_B = 1024;
}

__device__ float g_h    [(size_t)N_CAP * HC];
__device__ float g_asrc [N_CAP * HN];
__device__ float g_adst [N_CAP * HN];
__device__ int   g_deg  [N_CAP];
__device__ int   g_off  [N_CAP];
__device__ int   g_pos  [N_CAP];
__device__ int   g_bsum [128];
__device__ int   g_csr  [E_CAP];

__device__ __forceinline__ void edge_sd(const int* ei, int e, int E, int& s, int& d) {
    if (e < E) { s = ei[e]; d = ei[E + e]; }
    else       { s = d = e - E; }
}

// ---------------------------------------------------------------------------
__global__ void k_zero(int N) {
    int i = blockIdx.x * blockDim.x + threadIdx.x;
    if (i < N) g_deg[i] = 0;
}

// ---------------------------------------------------------------------------
// GEMM h = x@W, block = 128 rows x 64 cols (exactly one head), 256 threads,
// thread tile 8x4. Epilogue: fused dot with att_src/att_dst for this head.
__global__ void k_gemm(const float* __restrict__ x, const float* __restrict__ Wm,
                       const float* __restrict__ att_src,
                       const float* __restrict__ att_dst, int N) {
    __shared__ float xs[128][64];
    __shared__ float ws[64][64];
    int t = threadIdx.x;
    int brow = blockIdx.x * 128;
    int head = blockIdx.y;            // col block == head
    int bcol = head * 64;

#pragma unroll
    for (int i = 0; i < 8; i++) {
        int v = i * 256 + t;
        int r = v >> 4, k4 = v & 15;
        int gr = brow + r;
        float4 val = (gr < N) ? __ldg((const float4*)x + (size_t)gr * 16 + k4)
                              : make_float4(0.f, 0.f, 0.f, 0.f);
        *(float4*)&xs[r][k4 * 4] = val;
    }
#pragma unroll
    for (int i = 0; i < 4; i++) {
        int v = i * 256 + t;
        int k = v >> 4, c4 = v & 15;
        *(float4*)&ws[k][c4 * 4] =
            __ldg((const float4*)Wm + (size_t)k * (HC / 4) + (bcol >> 2) + c4);
    }
    __syncthreads();

    int ty = t >> 4, tx = t & 15;
    int r0 = ty * 8, c0 = tx * 4;
    float acc[8][4] = {};
#pragma unroll
    for (int k = 0; k < 64; k++) {
        float4 b = *(const float4*)&ws[k][c0];
#pragma unroll
        for (int i = 0; i < 8; i++) {
            float a = xs[r0 + i][k];
            acc[i][0] += a * b.x; acc[i][1] += a * b.y;
            acc[i][2] += a * b.z; acc[i][3] += a * b.w;
        }
    }

    // store h tile
#pragma unroll
    for (int i = 0; i < 8; i++) {
        int gr = brow + r0 + i;
        if (gr < N)
            *(float4*)&g_h[(size_t)gr * HC + bcol + c0] =
                make_float4(acc[i][0], acc[i][1], acc[i][2], acc[i][3]);
    }

    // fused attention coefficients for this head
    float4 avs = __ldg((const float4*)att_src + head * 16 + tx);
    float4 avd = __ldg((const float4*)att_dst + head * 16 + tx);
#pragma unroll
    for (int i = 0; i < 8; i++) {
        float ps = acc[i][0] * avs.x + acc[i][1] * avs.y +
                   acc[i][2] * avs.z + acc[i][3] * avs.w;
        float pd = acc[i][0] * avd.x + acc[i][1] * avd.y +
                   acc[i][2] * avd.z + acc[i][3] * avd.w;
#pragma unroll
        for (int o = 8; o; o >>= 1) {            // reduce over 16-lane tx group
            ps += __shfl_xor_sync(0xffffffffu, ps, o);
            pd += __shfl_xor_sync(0xffffffffu, pd, o);
        }
        int gr = brow + r0 + i;
        if (tx == 0 && gr < N) {
            g_asrc[gr * HN + head] = ps;
            g_adst[gr * HN + head] = pd;
        }
    }
}

// ---------------------------------------------------------------------------
__global__ void k_hist(const int* __restrict__ ei, int E, int Etot) {
    int e = blockIdx.x * blockDim.x + threadIdx.x;
    if (e >= Etot) return;
    int d = (e < E) ? ei[E + e] : (e - E);
    atomicAdd(&g_deg[d], 1);
}

__global__ void k_scan1(int N) {
    __shared__ int sm[SCAN_B];
    int i = blockIdx.x * SCAN_B + threadIdx.x;
    int v = (i < N) ? g_deg[i] : 0;
    sm[threadIdx.x] = v;
    __syncthreads();
#pragma unroll
    for (int o = 1; o < SCAN_B; o <<= 1) {
        int t = (threadIdx.x >= o) ? sm[threadIdx.x - o] : 0;
        __syncthreads();
        sm[threadIdx.x] += t;
        __syncthreads();
    }
    if (i < N) g_off[i] = sm[threadIdx.x] - v;     // exclusive within block
    if (threadIdx.x == SCAN_B - 1) g_bsum[blockIdx.x] = sm[SCAN_B - 1];
}

__global__ void k_scan2(int B) {
    if (threadIdx.x == 0) {
        int run = 0;
        for (int b = 0; b < B; b++) { int t = g_bsum[b]; g_bsum[b] = run; run += t; }
    }
}

__global__ void k_scan3(int N) {
    int i = blockIdx.x * SCAN_B + threadIdx.x;
    if (i < N) {
        int o = g_off[i] + g_bsum[blockIdx.x];
        g_off[i] = o;
        g_pos[i] = o;
    }
}

__global__ void k_scatter(const int* __restrict__ ei, int E, int Etot) {
    int e = blockIdx.x * blockDim.x + threadIdx.x;
    if (e >= Etot) return;
    int s, d;
    edge_sd(ei, e, E, s, d);
    int p = atomicAdd(&g_pos[d], 1);
    g_csr[p] = s;
}

// ---------------------------------------------------------------------------
// Fused per-dst: softmax over neighborhood + weighted feature gather +
// head mean + bias + residual + relu.  Block = 192 threads, one dst node.
__global__ void __launch_bounds__(192) k_agg(
    const float* __restrict__ x, const float* __restrict__ bias,
    float* __restrict__ y, int N) {
    __shared__ float s_m[HN], s_s[HN], s_ad[HN];
    __shared__ float4 s_red[192];

    int i = blockIdx.x;
    int tid = threadIdx.x;
    int off = g_off[i];
    int deg = g_deg[i];

    if (tid < HN) {
        int h = tid;
        float ad = g_adst[i * HN + h];
        s_ad[h] = ad;
        float mx = -3.4e38f;
        for (int e = off; e < off + deg; e++) {
            float v = g_asrc[g_csr[e] * HN + h] + ad;
            v = (v > 0.f) ? v : 0.2f * v;
            mx = fmaxf(mx, v);
        }
        s_m[h] = mx;
        float sum = 0.f;
        for (int e = off; e < off + deg; e++) {
            float v = g_asrc[g_csr[e] * HN + h] + ad;
            v = (v > 0.f) ? v : 0.2f * v;
            sum += expf(v - mx);
        }
        s_s[h] = sum;
    }
    __syncthreads();

    int h = tid >> 4;          // head 0..11
    int c4 = tid & 15;         // float4 within head channels
    float ad = s_ad[h], mh = s_m[h];
    float4 acc = make_float4(0.f, 0.f, 0.f, 0.f);
    for (int e = off; e < off + deg; e++) {
        int src = g_csr[e];
        float v = g_asrc[src * HN + h] + ad;
        v = (v > 0.f) ? v : 0.2f * v;
        float w = expf(v - mh);
        float4 hv = *(const float4*)(g_h + (size_t)src * HC + h * CD + c4 * 4);
        acc.x += w * hv.x; acc.y += w * hv.y;
        acc.z += w * hv.z; acc.w += w * hv.w;
    }
    float inv = 1.f / (s_s[h] + 1e-16f);
    acc.x *= inv; acc.y *= inv; acc.z *= inv; acc.w *= inv;
    s_red[tid] = acc;
    __syncthreads();

    if (tid < 16) {
        float4 sum = make_float4(0.f, 0.f, 0.f, 0.f);
#pragma unroll
        for (int hh = 0; hh < HN; hh++) {
            float4 v = s_red[hh * 16 + tid];
            sum.x += v.x; sum.y += v.y; sum.z += v.z; sum.w += v.w;
        }
        const float invH = 1.0f / (float)HN;
        float4 xv = __ldg((const float4*)x + (size_t)i * 16 + tid);
        float4 bv = __ldg((const float4*)bias + tid);
        float4 r;
        r.x = fmaxf(xv.x + sum.x * invH + bv.x, 0.f);
        r.y = fmaxf(xv.y + sum.y * invH + bv.y, 0.f);
        r.z = fmaxf(xv.z + sum.z * invH + bv.z, 0.f);
        r.w = fmaxf(xv.w + sum.w * invH + bv.w, 0.f);
        ((float4*)y)[(size_t)i * 16 + tid] = r;
    }
}

// ---------------------------------------------------------------------------
extern "C" void kernel_launch(void* const* d_in, const int* in_sizes, int n_in,
                              void* d_out, int out_size) {
    (void)n_in; (void)out_size;
    const float* x    = (const float*)d_in[0];
    const int*   ei   = (const int*)d_in[1];
    const float* Wm   = (const float*)d_in[2];
    const float* a_s  = (const float*)d_in[3];
    const float* a_d  = (const float*)d_in[4];
    const float* bias = (const float*)d_in[5];

    int N = in_sizes[0] / CD;
    int E = in_sizes[1] / 2;
    if (N > N_CAP) N = N_CAP;
    if (E + N > E_CAP) E = E_CAP - N;
    int Etot = E + N;
    int B = (N + SCAN_B - 1) / SCAN_B;

    k_zero<<<(N + 255) / 256, 256>>>(N);

    dim3 gg((N + 127) / 128, HN);
    k_gemm<<<gg, 256>>>(x, Wm, a_s, a_d, N);

    k_hist<<<(Etot + 255) / 256, 256>>>(ei, E, Etot);
    k_scan1<<<B, SCAN_B>>>(N);
    k_scan2<<<1, 32>>>(B);
    k_scan3<<<B, SCAN_B>>>(N);
    k_scatter<<<(Etot + 255) / 256, 256>>>(ei, E, Etot);

    k_agg<<<N, 192>>>(x, bias, (float*)d_out, N);
}